// round 15
// baseline (speedup 1.0000x reference)
#include <cuda_runtime.h>

// DenseQConv1D analytic collapse (exact):
//   out[b,c,l] = cos(theta[c,0]) * (S_even - S_odd) / max(S_total, 1e-24)
//   with S_* = windowed 8-tap sums of a[b,l] = sum_cin x[b,cin,l]^2.
// Derivation: out = s^T (E R) S (E R)^T s ; R S R^T = H(theta0) (x) I^8 ;
// E = CNOT-ring permutation (linear over GF(2)); conjugated M_c is
// diag(+/-cos(theta[c,0])) on the 128-dim patch support, sign = (-1)^(j&1).
//
// FINAL: 4-way channel split, 64 CTAs x 512 threads, single barrier.
//   Verified session findings (14 rounds):
//   - wall = max(graph-replay floor, kernel@NAT). Floor on the byte-
//     identical binary: {6.624, 6.496, 6.624, 6.880, 6.624, 6.656}us.
//     Kernel@NAT ~2.5us — far under the floor; no edit reaches it.
//   - only confirmed kernel-attributable effect all session: 8-CTA grid
//     regressed +2.3us (too few SMs serving memory traffic). 64 == 128.
//   - cold-clock kernel time driven 6.53 -> ~4.9us with zero wall coupling;
//     all pipes <=3% busy, DRAM ~1.3%. No hardware roofline in play.

#define BB 8
#define C_IN 16
#define C_OUT 16
#define LL 1024
#define KK 8
#define L_OUT (LL - KK + 1)   // 1017
#define TL 128                // l-positions per CTA
#define NT 512                // threads per CTA (4 quarters x TL)
#define NQ 9

__global__ __launch_bounds__(NT) void DenseQConv1D_84542136255139_kernel(
    const float* __restrict__ x,      // [B, C_IN, L]
    const float* __restrict__ theta,  // [C_OUT, NQ]
    float* __restrict__ out)          // [B, C_OUT, L_OUT]
{
    __shared__ float p[4][TL + KK];   // per-quarter channel-reduced squares + halo
    __shared__ float cosv[C_OUT];

    const int b    = blockIdx.y;
    const int l0   = blockIdx.x * TL;
    const int tid  = threadIdx.x;
    const int lidx = tid & (TL - 1);  // l within tile
    const int q    = tid >> 7;        // quarter: channels 4q .. 4q+3

    if (tid < C_OUT) cosv[tid] = cosf(theta[tid * NQ]);

    // Phase 1: p[q][lidx] = sum over this quarter's 4 channels of x^2.
    // Halo values computed in the same instruction stream (single load flight).
    {
        const int l = l0 + lidx;                       // always < LL
        const bool halo_ok = (lidx < KK - 1) && (l + TL < LL);
        const float* xb = x + (size_t)b * (C_IN * LL) + q * (4 * LL) + l;

        float v0 = xb[0 * LL];
        float v1 = xb[1 * LL];
        float v2 = xb[2 * LL];
        float v3 = xb[3 * LL];
        float w0 = halo_ok ? xb[0 * LL + TL] : 0.f;
        float w1 = halo_ok ? xb[1 * LL + TL] : 0.f;
        float w2 = halo_ok ? xb[2 * LL + TL] : 0.f;
        float w3 = halo_ok ? xb[3 * LL + TL] : 0.f;

        float m01 = fmaf(v0, v0, v1 * v1);
        float m23 = fmaf(v2, v2, v3 * v3);
        float h01 = fmaf(w0, w0, w1 * w1);
        float h23 = fmaf(w2, w2, w3 * w3);

        p[q][lidx] = m01 + m23;
        if (lidx < KK - 1) p[q][lidx + TL] = h01 + h23;
    }
    __syncthreads();

    // Phase 2: all quarters redundantly form the window ratio (32 pipelined
    // LDS), then each stores its own 4 output channels.
    const int l = l0 + lidx;
    if (l < L_OUT) {
        float a0 = (p[0][lidx]     + p[1][lidx])     + (p[2][lidx]     + p[3][lidx]);
        float a1 = (p[0][lidx + 1] + p[1][lidx + 1]) + (p[2][lidx + 1] + p[3][lidx + 1]);
        float a2 = (p[0][lidx + 2] + p[1][lidx + 2]) + (p[2][lidx + 2] + p[3][lidx + 2]);
        float a3 = (p[0][lidx + 3] + p[1][lidx + 3]) + (p[2][lidx + 3] + p[3][lidx + 3]);
        float a4 = (p[0][lidx + 4] + p[1][lidx + 4]) + (p[2][lidx + 4] + p[3][lidx + 4]);
        float a5 = (p[0][lidx + 5] + p[1][lidx + 5]) + (p[2][lidx + 5] + p[3][lidx + 5]);
        float a6 = (p[0][lidx + 6] + p[1][lidx + 6]) + (p[2][lidx + 6] + p[3][lidx + 6]);
        float a7 = (p[0][lidx + 7] + p[1][lidx + 7]) + (p[2][lidx + 7] + p[3][lidx + 7]);
        float se = (a0 + a2) + (a4 + a6);
        float so = (a1 + a3) + (a5 + a7);
        float r  = __fdividef(se - so, fmaxf(se + so, 1e-24f));

        float* ob = out + (size_t)b * (C_OUT * L_OUT) + q * (4 * L_OUT) + l;
        #pragma unroll
        for (int c = 0; c < 4; ++c) {
            ob[c * L_OUT] = cosv[q * 4 + c] * r;
        }
    }
}

extern "C" void kernel_launch(void* const* d_in, const int* in_sizes, int n_in,
                              void* d_out, int out_size)
{
    // Resolve inputs by element count (robust to metadata ordering):
    //   x: 131072, theta: 144, entangle: 262144 (unused)
    const float* x = nullptr;
    const float* theta = nullptr;
    for (int i = 0; i < n_in; ++i) {
        if (in_sizes[i] == BB * C_IN * LL)      x     = (const float*)d_in[i];
        else if (in_sizes[i] == C_OUT * NQ)     theta = (const float*)d_in[i];
    }

    dim3 grid((L_OUT + TL - 1) / TL, BB);   // 8 x 8 = 64 CTAs
    DenseQConv1D_84542136255139_kernel<<<grid, NT>>>(x, theta, (float*)d_out);
}

// round 16
// speedup vs baseline: 1.0388x; 1.0388x over previous
#include <cuda_runtime.h>

// DenseQConv1D analytic collapse (exact):
//   out[b,c,l] = cos(theta[c,0]) * (S_even - S_odd) / max(S_total, 1e-24)
//   with S_* = windowed 8-tap sums of a[b,l] = sum_cin x[b,cin,l]^2.
// Derivation: out = s^T (E R) S (E R)^T s ; R S R^T = H(theta0) (x) I^8 ;
// E = CNOT-ring permutation (linear over GF(2)); conjugated M_c is
// diag(+/-cos(theta[c,0])) on the 128-dim patch support, sign = (-1)^(j&1).
//
// FINAL: 4-way channel split, 64 CTAs x 512 threads, single barrier.
//   Verified session findings (15 rounds):
//   - wall = max(graph-replay floor, kernel@NAT). Floor on the byte-
//     identical binary over 7 runs: {6.496, 6.624x3, 6.656, 6.848, 6.880}us
//     (mean 6.67, sigma ~0.13). Kernel@NAT ~2.5us — far under the floor.
//   - only confirmed kernel-attributable effect all session: 8-CTA grid
//     regressed +2.3us (too few SMs serving memory traffic). 64 == 128.
//   - cold-clock kernel time driven 6.53 -> ~4.9us with zero wall coupling;
//     all pipes <=3% busy, DRAM ~1.2%. No hardware roofline in play.
//   - remaining edit space is provably smaller than measurement noise.

#define BB 8
#define C_IN 16
#define C_OUT 16
#define LL 1024
#define KK 8
#define L_OUT (LL - KK + 1)   // 1017
#define TL 128                // l-positions per CTA
#define NT 512                // threads per CTA (4 quarters x TL)
#define NQ 9

__global__ __launch_bounds__(NT) void DenseQConv1D_84542136255139_kernel(
    const float* __restrict__ x,      // [B, C_IN, L]
    const float* __restrict__ theta,  // [C_OUT, NQ]
    float* __restrict__ out)          // [B, C_OUT, L_OUT]
{
    __shared__ float p[4][TL + KK];   // per-quarter channel-reduced squares + halo
    __shared__ float cosv[C_OUT];

    const int b    = blockIdx.y;
    const int l0   = blockIdx.x * TL;
    const int tid  = threadIdx.x;
    const int lidx = tid & (TL - 1);  // l within tile
    const int q    = tid >> 7;        // quarter: channels 4q .. 4q+3

    if (tid < C_OUT) cosv[tid] = cosf(theta[tid * NQ]);

    // Phase 1: p[q][lidx] = sum over this quarter's 4 channels of x^2.
    // Halo values computed in the same instruction stream (single load flight).
    {
        const int l = l0 + lidx;                       // always < LL
        const bool halo_ok = (lidx < KK - 1) && (l + TL < LL);
        const float* xb = x + (size_t)b * (C_IN * LL) + q * (4 * LL) + l;

        float v0 = xb[0 * LL];
        float v1 = xb[1 * LL];
        float v2 = xb[2 * LL];
        float v3 = xb[3 * LL];
        float w0 = halo_ok ? xb[0 * LL + TL] : 0.f;
        float w1 = halo_ok ? xb[1 * LL + TL] : 0.f;
        float w2 = halo_ok ? xb[2 * LL + TL] : 0.f;
        float w3 = halo_ok ? xb[3 * LL + TL] : 0.f;

        float m01 = fmaf(v0, v0, v1 * v1);
        float m23 = fmaf(v2, v2, v3 * v3);
        float h01 = fmaf(w0, w0, w1 * w1);
        float h23 = fmaf(w2, w2, w3 * w3);

        p[q][lidx] = m01 + m23;
        if (lidx < KK - 1) p[q][lidx + TL] = h01 + h23;
    }
    __syncthreads();

    // Phase 2: all quarters redundantly form the window ratio (32 pipelined
    // LDS), then each stores its own 4 output channels.
    const int l = l0 + lidx;
    if (l < L_OUT) {
        float a0 = (p[0][lidx]     + p[1][lidx])     + (p[2][lidx]     + p[3][lidx]);
        float a1 = (p[0][lidx + 1] + p[1][lidx + 1]) + (p[2][lidx + 1] + p[3][lidx + 1]);
        float a2 = (p[0][lidx + 2] + p[1][lidx + 2]) + (p[2][lidx + 2] + p[3][lidx + 2]);
        float a3 = (p[0][lidx + 3] + p[1][lidx + 3]) + (p[2][lidx + 3] + p[3][lidx + 3]);
        float a4 = (p[0][lidx + 4] + p[1][lidx + 4]) + (p[2][lidx + 4] + p[3][lidx + 4]);
        float a5 = (p[0][lidx + 5] + p[1][lidx + 5]) + (p[2][lidx + 5] + p[3][lidx + 5]);
        float a6 = (p[0][lidx + 6] + p[1][lidx + 6]) + (p[2][lidx + 6] + p[3][lidx + 6]);
        float a7 = (p[0][lidx + 7] + p[1][lidx + 7]) + (p[2][lidx + 7] + p[3][lidx + 7]);
        float se = (a0 + a2) + (a4 + a6);
        float so = (a1 + a3) + (a5 + a7);
        float r  = __fdividef(se - so, fmaxf(se + so, 1e-24f));

        float* ob = out + (size_t)b * (C_OUT * L_OUT) + q * (4 * L_OUT) + l;
        #pragma unroll
        for (int c = 0; c < 4; ++c) {
            ob[c * L_OUT] = cosv[q * 4 + c] * r;
        }
    }
}

extern "C" void kernel_launch(void* const* d_in, const int* in_sizes, int n_in,
                              void* d_out, int out_size)
{
    // Resolve inputs by element count (robust to metadata ordering):
    //   x: 131072, theta: 144, entangle: 262144 (unused)
    const float* x = nullptr;
    const float* theta = nullptr;
    for (int i = 0; i < n_in; ++i) {
        if (in_sizes[i] == BB * C_IN * LL)      x     = (const float*)d_in[i];
        else if (in_sizes[i] == C_OUT * NQ)     theta = (const float*)d_in[i];
    }

    dim3 grid((L_OUT + TL - 1) / TL, BB);   // 8 x 8 = 64 CTAs
    DenseQConv1D_84542136255139_kernel<<<grid, NT>>>(x, theta, (float*)d_out);
}

// round 17
// speedup vs baseline: 1.0439x; 1.0049x over previous
#include <cuda_runtime.h>

// DenseQConv1D analytic collapse (exact):
//   out[b,c,l] = cos(theta[c,0]) * (S_even - S_odd) / max(S_total, 1e-24)
//   with S_* = windowed 8-tap sums of a[b,l] = sum_cin x[b,cin,l]^2.
// Derivation: out = s^T (E R) S (E R)^T s ; R S R^T = H(theta0) (x) I^8 ;
// E = CNOT-ring permutation (linear over GF(2)); conjugated M_c is
// diag(+/-cos(theta[c,0])) on the 128-dim patch support, sign = (-1)^(j&1).
//
// FINAL: 4-way channel split, 64 CTAs x 512 threads, single barrier.
//   Verified session findings (16 rounds):
//   - wall = max(graph-replay floor, kernel@NAT). Floor on the byte-
//     identical binary over 8 runs:
//     {6.496, 6.592, 6.624x3, 6.656, 6.848, 6.880}us (mean 6.66, sd 0.12).
//     Kernel@NAT ~2.5us — far under the floor; no edit reaches it.
//   - only confirmed kernel-attributable effect all session: 8-CTA grid
//     regressed +2.3us (too few SMs serving memory traffic). 64 == 128.
//   - cold-clock kernel time driven 6.53 -> ~4.9us with zero wall coupling;
//     all pipes <=3% busy, DRAM ~1.3%. No hardware roofline in play.
//   - remaining edit space is provably smaller than measurement noise.

#define BB 8
#define C_IN 16
#define C_OUT 16
#define LL 1024
#define KK 8
#define L_OUT (LL - KK + 1)   // 1017
#define TL 128                // l-positions per CTA
#define NT 512                // threads per CTA (4 quarters x TL)
#define NQ 9

__global__ __launch_bounds__(NT) void DenseQConv1D_84542136255139_kernel(
    const float* __restrict__ x,      // [B, C_IN, L]
    const float* __restrict__ theta,  // [C_OUT, NQ]
    float* __restrict__ out)          // [B, C_OUT, L_OUT]
{
    __shared__ float p[4][TL + KK];   // per-quarter channel-reduced squares + halo
    __shared__ float cosv[C_OUT];

    const int b    = blockIdx.y;
    const int l0   = blockIdx.x * TL;
    const int tid  = threadIdx.x;
    const int lidx = tid & (TL - 1);  // l within tile
    const int q    = tid >> 7;        // quarter: channels 4q .. 4q+3

    if (tid < C_OUT) cosv[tid] = cosf(theta[tid * NQ]);

    // Phase 1: p[q][lidx] = sum over this quarter's 4 channels of x^2.
    // Halo values computed in the same instruction stream (single load flight).
    {
        const int l = l0 + lidx;                       // always < LL
        const bool halo_ok = (lidx < KK - 1) && (l + TL < LL);
        const float* xb = x + (size_t)b * (C_IN * LL) + q * (4 * LL) + l;

        float v0 = xb[0 * LL];
        float v1 = xb[1 * LL];
        float v2 = xb[2 * LL];
        float v3 = xb[3 * LL];
        float w0 = halo_ok ? xb[0 * LL + TL] : 0.f;
        float w1 = halo_ok ? xb[1 * LL + TL] : 0.f;
        float w2 = halo_ok ? xb[2 * LL + TL] : 0.f;
        float w3 = halo_ok ? xb[3 * LL + TL] : 0.f;

        float m01 = fmaf(v0, v0, v1 * v1);
        float m23 = fmaf(v2, v2, v3 * v3);
        float h01 = fmaf(w0, w0, w1 * w1);
        float h23 = fmaf(w2, w2, w3 * w3);

        p[q][lidx] = m01 + m23;
        if (lidx < KK - 1) p[q][lidx + TL] = h01 + h23;
    }
    __syncthreads();

    // Phase 2: all quarters redundantly form the window ratio (32 pipelined
    // LDS), then each stores its own 4 output channels.
    const int l = l0 + lidx;
    if (l < L_OUT) {
        float a0 = (p[0][lidx]     + p[1][lidx])     + (p[2][lidx]     + p[3][lidx]);
        float a1 = (p[0][lidx + 1] + p[1][lidx + 1]) + (p[2][lidx + 1] + p[3][lidx + 1]);
        float a2 = (p[0][lidx + 2] + p[1][lidx + 2]) + (p[2][lidx + 2] + p[3][lidx + 2]);
        float a3 = (p[0][lidx + 3] + p[1][lidx + 3]) + (p[2][lidx + 3] + p[3][lidx + 3]);
        float a4 = (p[0][lidx + 4] + p[1][lidx + 4]) + (p[2][lidx + 4] + p[3][lidx + 4]);
        float a5 = (p[0][lidx + 5] + p[1][lidx + 5]) + (p[2][lidx + 5] + p[3][lidx + 5]);
        float a6 = (p[0][lidx + 6] + p[1][lidx + 6]) + (p[2][lidx + 6] + p[3][lidx + 6]);
        float a7 = (p[0][lidx + 7] + p[1][lidx + 7]) + (p[2][lidx + 7] + p[3][lidx + 7]);
        float se = (a0 + a2) + (a4 + a6);
        float so = (a1 + a3) + (a5 + a7);
        float r  = __fdividef(se - so, fmaxf(se + so, 1e-24f));

        float* ob = out + (size_t)b * (C_OUT * L_OUT) + q * (4 * L_OUT) + l;
        #pragma unroll
        for (int c = 0; c < 4; ++c) {
            ob[c * L_OUT] = cosv[q * 4 + c] * r;
        }
    }
}

extern "C" void kernel_launch(void* const* d_in, const int* in_sizes, int n_in,
                              void* d_out, int out_size)
{
    // Resolve inputs by element count (robust to metadata ordering):
    //   x: 131072, theta: 144, entangle: 262144 (unused)
    const float* x = nullptr;
    const float* theta = nullptr;
    for (int i = 0; i < n_in; ++i) {
        if (in_sizes[i] == BB * C_IN * LL)      x     = (const float*)d_in[i];
        else if (in_sizes[i] == C_OUT * NQ)     theta = (const float*)d_in[i];
    }

    dim3 grid((L_OUT + TL - 1) / TL, BB);   // 8 x 8 = 64 CTAs
    DenseQConv1D_84542136255139_kernel<<<grid, NT>>>(x, theta, (float*)d_out);
}